// round 1
// baseline (speedup 1.0000x reference)
#include <cuda_runtime.h>

#define N_NODES 20000
#define N_EDGES 320000

// ---------------- device scratch (module-scope globals; no runtime alloc) ---
__device__ float g_f [N_NODES * 256];     // f0|f1 (deg/attr/inv8 folded in)
__device__ float g_ew[N_EDGES * 256];     // per-edge MLP weights (wa|wb|wc|wd)
__device__ int   g_cnt[N_NODES];
__device__ int   g_off[N_NODES + 1];
__device__ int   g_cur[N_NODES];
__device__ int   g_eid[N_EDGES];

// ---------------- constants -------------------------------------------------
#define INV8        0.125f                 // 1/sqrt(64)
#define INV_SQRT10  0.3162277660168379f
#define INV10       0.1f                   // 1/sqrt(100)
#define INV_SQRT3   0.5773502691896258f
#define INV_SQRT128 0.08838834764831845f
#define C_S         0.3826834323650898f    // sin(pi/8)
#define C_X         0.9238795325112867f    // cos(pi/8)

// ---------------- packed f32x2 helpers (sm_100+) ---------------------------
__device__ __forceinline__ unsigned long long pk2(float x) {
    unsigned long long d; unsigned r = __float_as_uint(x);
    asm("mov.b64 %0, {%1, %1};" : "=l"(d) : "r"(r));
    return d;
}
__device__ __forceinline__ unsigned long long ffma2(unsigned long long a,
                                                    unsigned long long b,
                                                    unsigned long long c) {
    unsigned long long d;
    asm("fma.rn.f32x2 %0, %1, %2, %3;" : "=l"(d) : "l"(a), "l"(b), "l"(c));
    return d;
}
__device__ __forceinline__ float f2lo(unsigned long long v) {
    return __uint_as_float((unsigned)(v & 0xffffffffull));
}
__device__ __forceinline__ float f2hi(unsigned long long v) {
    return __uint_as_float((unsigned)(v >> 32));
}

// ============================================================================
// K1: node self-interaction.  For 8 nodes per block compute
//   f = fctp(x, W_li) * attr * 1/8 * deg_isqrt   -> g_f
//   m = fctp(x, W_lm) * attr * 1/8 * sin(pi/8)   -> d_out (pull kernel adds o)
// dyn smem: 4 weight mats (64KB) + x tile (8 x 257)
// ============================================================================
__global__ __launch_bounds__(256) void k_node(
    const float* __restrict__ x, const float* __restrict__ attr,
    const float* __restrict__ deg,
    const float* __restrict__ Wli0, const float* __restrict__ Wli1,
    const float* __restrict__ Wlm0, const float* __restrict__ Wlm1,
    float* __restrict__ out)
{
    extern __shared__ float sm[];
    float* sWf0 = sm;             // 4096
    float* sWf1 = sm + 4096;
    float* sWm0 = sm + 8192;
    float* sWm1 = sm + 12288;
    float* sx   = sm + 16384;     // 8 * 257

    int t = threadIdx.x;
    for (int i = t; i < 4096; i += 256) {
        sWf0[i] = Wli0[i]; sWf1[i] = Wli1[i];
        sWm0[i] = Wlm0[i]; sWm1[i] = Wlm1[i];
    }
    int nb = blockIdx.x * 8;
    for (int i = t; i < 8 * 256; i += 256) {
        int node = i >> 8, cc = i & 255;
        sx[node * 257 + cc] = x[(nb + node) * 256 + cc];
    }
    __syncthreads();

    int c = t;
    bool isS = (c < 64);
    int k = isS ? c : (c - 64) / 3;
    int m = isS ? 0 : (c - 64) % 3;
    int xoff = isS ? 0 : (64 + m);
    int xstr = isS ? 1 : 3;
    const float* wf = (isS ? sWf0 : sWf1) + k;
    const float* wm = (isS ? sWm0 : sWm1) + k;
    const float* xp = sx + xoff;

    float accf[8], accm[8];
#pragma unroll
    for (int i = 0; i < 8; i++) { accf[i] = 0.f; accm[i] = 0.f; }

#pragma unroll 4
    for (int u = 0; u < 64; u++) {
        float vf = wf[u * 64];
        float vm = wm[u * 64];
#pragma unroll
        for (int i = 0; i < 8; i++) {
            float xv = xp[i * 257 + u * xstr];
            accf[i] = fmaf(xv, vf, accf[i]);
            accm[i] = fmaf(xv, vm, accm[i]);
        }
    }
#pragma unroll
    for (int i = 0; i < 8; i++) {
        int n = nb + i;
        float a  = attr[n];
        float sf = INV8 * a * rsqrtf(deg[n]);
        float sc = INV8 * a * C_S;
        g_f[n * 256 + c] = accf[i] * sf;
        out[n * 256 + c] = accm[i] * sc;
    }
}

// ============================================================================
// CSR build kernels
// ============================================================================
__global__ __launch_bounds__(256) void k_zero() {
    int i = blockIdx.x * 256 + threadIdx.x;
    if (i < N_NODES) g_cnt[i] = 0;
}
__global__ __launch_bounds__(256) void k_hist(const int* __restrict__ dst) {
    int i = blockIdx.x * 256 + threadIdx.x;
    if (i < N_EDGES) atomicAdd(&g_cnt[dst[i]], 1);
}
__global__ __launch_bounds__(1024) void k_scan() {
    int t = threadIdx.x, lane = t & 31, wid = t >> 5;
    __shared__ int wsum[32];
    __shared__ int carry;
    if (t == 0) carry = 0;
    __syncthreads();
    for (int base = 0; base < N_NODES; base += 1024) {
        int i = base + t;
        int v = (i < N_NODES) ? g_cnt[i] : 0;
        int x = v;
#pragma unroll
        for (int d = 1; d < 32; d <<= 1) {
            int y = __shfl_up_sync(0xffffffffu, x, d);
            if (lane >= d) x += y;
        }
        if (lane == 31) wsum[wid] = x;
        __syncthreads();
        if (wid == 0) {
            int s = wsum[lane];
#pragma unroll
            for (int d = 1; d < 32; d <<= 1) {
                int y = __shfl_up_sync(0xffffffffu, s, d);
                if (lane >= d) s += y;
            }
            wsum[lane] = s;
        }
        __syncthreads();
        int excl = carry + (wid ? wsum[wid - 1] : 0) + x - v;
        if (i < N_NODES) { g_off[i] = excl; g_cur[i] = excl; }
        int tot = wsum[31];
        __syncthreads();
        if (t == 0) carry += tot;
        __syncthreads();
    }
    if (t == 0) g_off[N_NODES] = carry;
}
__global__ __launch_bounds__(256) void k_fill(const int* __restrict__ dst) {
    int i = blockIdx.x * 256 + threadIdx.x;
    if (i < N_EDGES) {
        int d = dst[i];
        int p = atomicAdd(&g_cur[d], 1);
        g_eid[p] = i;
    }
}

// ============================================================================
// K2: edge MLP  ew = silu(elen @ W1 / sqrt(10)) @ W2 / 10   -> g_ew
// 64 edges per block, fp32 with packed f32x2 FMAs in the 100x256 GEMM.
// ============================================================================
__global__ __launch_bounds__(256, 2) void k_mlp(
    const float* __restrict__ elen, const float* __restrict__ W1,
    const float* __restrict__ W2)
{
    __shared__ __align__(16) float s_W1[1000];
    __shared__ __align__(16) float s_hT[104][64];   // k-major h, rows 100..103 = 0
    __shared__ __align__(16) float s_W2[8 * 256];   // one 8-row K chunk

    int t = threadIdx.x;
    int e0 = blockIdx.x * 64;

    for (int i = t; i < 1000; i += 256) s_W1[i] = W1[i];
    // zero pad rows of hT
    s_hT[100 + (t >> 6)][t & 63] = 0.0f;
    __syncthreads();

    // ---- layer 1 + silu ----
    {
        int e  = t & 63;
        int j0 = t >> 6;
        float el[10];
        const float* ep = elen + (e0 + e) * 10;
#pragma unroll
        for (int b = 0; b < 10; b++) el[b] = ep[b];
#pragma unroll 1
        for (int it = 0; it < 25; it++) {
            int j = j0 + 4 * it;
            float acc = 0.f;
#pragma unroll
            for (int b = 0; b < 10; b++) acc = fmaf(el[b], s_W1[b * 100 + j], acc);
            float xx = acc * INV_SQRT10;
            float hv = xx / (1.0f + __expf(-xx));   // silu
            s_hT[j][e] = hv;
        }
    }
    __syncthreads();

    // ---- layer 2: (64 x 104) @ (104 x 256), thread tile 8 edges x 8 cols ----
    int w = t >> 5;          // warp id -> edge octet
    int lane = t & 31;       // -> col octet
    unsigned long long acc[32];
#pragma unroll
    for (int i = 0; i < 32; i++) acc[i] = 0ull;

    for (int kc = 0; kc < 13; kc++) {
        for (int i = t; i < 2048; i += 256) {
            int kk = i >> 8, col = i & 255;
            int kg = kc * 8 + kk;
            s_W2[i] = (kg < 100) ? W2[kg * 256 + col] : 0.0f;
        }
        __syncthreads();
#pragma unroll
        for (int kk = 0; kk < 8; kk++) {
            const float4* ap = (const float4*)&s_hT[kc * 8 + kk][w * 8];
            float4 a0 = ap[0], a1 = ap[1];
            unsigned long long A[8];
            A[0] = pk2(a0.x); A[1] = pk2(a0.y); A[2] = pk2(a0.z); A[3] = pk2(a0.w);
            A[4] = pk2(a1.x); A[5] = pk2(a1.y); A[6] = pk2(a1.z); A[7] = pk2(a1.w);
            const ulonglong2* bp = (const ulonglong2*)&s_W2[kk * 256 + lane * 8];
            ulonglong2 b0 = bp[0], b1 = bp[1];
#pragma unroll
            for (int i = 0; i < 8; i++) {
                acc[i * 4 + 0] = ffma2(A[i], b0.x, acc[i * 4 + 0]);
                acc[i * 4 + 1] = ffma2(A[i], b0.y, acc[i * 4 + 1]);
                acc[i * 4 + 2] = ffma2(A[i], b1.x, acc[i * 4 + 2]);
                acc[i * 4 + 3] = ffma2(A[i], b1.y, acc[i * 4 + 3]);
            }
        }
        __syncthreads();
    }

#pragma unroll
    for (int i = 0; i < 8; i++) {
        float* op = g_ew + (size_t)(e0 + w * 8 + i) * 256 + lane * 8;
        float4 v0, v1;
        v0.x = f2lo(acc[i * 4 + 0]) * INV10; v0.y = f2hi(acc[i * 4 + 0]) * INV10;
        v0.z = f2lo(acc[i * 4 + 1]) * INV10; v0.w = f2hi(acc[i * 4 + 1]) * INV10;
        v1.x = f2lo(acc[i * 4 + 2]) * INV10; v1.y = f2hi(acc[i * 4 + 2]) * INV10;
        v1.z = f2lo(acc[i * 4 + 3]) * INV10; v1.w = f2hi(acc[i * 4 + 3]) * INV10;
        ((float4*)op)[0] = v0;
        ((float4*)op)[1] = v1;
    }
}

// ============================================================================
// K3: pull kernel. One warp per destination node: recompute messages per
// incident edge, accumulate s_mid/v_mid in registers, then per-node
// 128x64 GEMM with W_lo, add c_x * o into d_out.
// dyn smem: W_lo0 + W_lo1 (64KB) + per-warp staging (8 x 128 float4)
// ============================================================================
__global__ __launch_bounds__(256) void k_pull(
    const float* __restrict__ attr, const float* __restrict__ deg,
    const float* __restrict__ eattr, const int* __restrict__ esrc,
    const float* __restrict__ Wlo0, const float* __restrict__ Wlo1,
    float* __restrict__ out)
{
    extern __shared__ float sm[];
    float* sW0  = sm;               // 128*64
    float* sW1  = sm + 8192;        // 128*64
    float* s_sv = sm + 16384;       // 8 warps * 512 floats (128 x float4)

    int t = threadIdx.x;
    for (int i = t; i < 8192; i += 256) { sW0[i] = Wlo0[i]; sW1[i] = Wlo1[i]; }
    __syncthreads();

    int w = t >> 5, lane = t & 31;
    int n = blockIdx.x * 8 + w;
    int beg = g_off[n], end = g_off[n + 1];

    float sa0 = 0.f, sa1 = 0.f, sb0 = 0.f, sb1 = 0.f;
    float va0x=0.f,va0y=0.f,va0z=0.f, va1x=0.f,va1y=0.f,va1z=0.f;
    float vb0x=0.f,vb0y=0.f,vb0z=0.f, vb1x=0.f,vb1y=0.f,vb1z=0.f;

    for (int ei = beg; ei < end; ei++) {
        int e   = g_eid[ei];
        int src = esrc[e];
        float4 ea = __ldg((const float4*)(eattr) + e);
        float y0 = ea.x, y1x = ea.y, y1y = ea.z, y1z = ea.w;
        const float* fp = g_f  + src * 256;
        const float* wp = g_ew + (size_t)e * 256;

        float2 G0 = *(const float2*)(fp + 2 * lane);
        float2 Ga = *(const float2*)(fp + 64 + 6 * lane);
        float2 Gb = *(const float2*)(fp + 64 + 6 * lane + 2);
        float2 Gc = *(const float2*)(fp + 64 + 6 * lane + 4);
        float2 WA = *(const float2*)(wp + 2 * lane);
        float2 WB = *(const float2*)(wp + 64 + 2 * lane);
        float2 WC = *(const float2*)(wp + 128 + 2 * lane);
        float2 WD = *(const float2*)(wp + 192 + 2 * lane);

        // u = 2*lane
        {
            float g1x = Ga.x, g1y = Ga.y, g1z = Gb.x;
            float d3 = fmaf(g1x, y1x, fmaf(g1y, y1y, g1z * y1z));
            sa0 = fmaf(WA.x * G0.x, y0, sa0);
            sb0 = fmaf(WB.x, d3, sb0);
            float cg = WC.x * G0.x;
            va0x = fmaf(cg, y1x, va0x); va0y = fmaf(cg, y1y, va0y); va0z = fmaf(cg, y1z, va0z);
            float dg = WD.x * y0;
            vb0x = fmaf(dg, g1x, vb0x); vb0y = fmaf(dg, g1y, vb0y); vb0z = fmaf(dg, g1z, vb0z);
        }
        // u = 2*lane + 1
        {
            float g1x = Gb.y, g1y = Gc.x, g1z = Gc.y;
            float d3 = fmaf(g1x, y1x, fmaf(g1y, y1y, g1z * y1z));
            sa1 = fmaf(WA.y * G0.y, y0, sa1);
            sb1 = fmaf(WB.y, d3, sb1);
            float cg = WC.y * G0.y;
            va1x = fmaf(cg, y1x, va1x); va1y = fmaf(cg, y1y, va1y); va1z = fmaf(cg, y1z, va1z);
            float dg = WD.y * y0;
            vb1x = fmaf(dg, g1x, vb1x); vb1y = fmaf(dg, g1y, vb1y); vb1z = fmaf(dg, g1z, vb1z);
        }
    }

    // stage [s, v0, v1, v2] per u-row (rows 0..63 = a-part, 64..127 = b-part)
    float a = attr[n];
    float scale = a * rsqrtf(deg[n]) * INV_SQRT128;
    float scb   = scale * INV_SQRT3;
    float4* sv = (float4*)(s_sv + w * 512);
    sv[2 * lane]      = make_float4(sa0 * scale, va0x * scale, va0y * scale, va0z * scale);
    sv[2 * lane + 1]  = make_float4(sa1 * scale, va1x * scale, va1y * scale, va1z * scale);
    sv[64 + 2 * lane]     = make_float4(sb0 * scb, vb0x * scale, vb0y * scale, vb0z * scale);
    sv[64 + 2 * lane + 1] = make_float4(sb1 * scb, vb1x * scale, vb1y * scale, vb1z * scale);
    __syncwarp();

    // per-node GEMM: o0[k] (k = 2*lane, 2*lane+1) and o1[k][m]
    float o0a = 0.f, o0b = 0.f;
    float o1ax=0.f,o1ay=0.f,o1az=0.f, o1bx=0.f,o1by=0.f,o1bz=0.f;
#pragma unroll 4
    for (int u = 0; u < 128; u++) {
        float4 svu = sv[u];
        float2 w0 = *(const float2*)(sW0 + u * 64 + 2 * lane);
        float2 w1 = *(const float2*)(sW1 + u * 64 + 2 * lane);
        o0a = fmaf(svu.x, w0.x, o0a);
        o0b = fmaf(svu.x, w0.y, o0b);
        o1ax = fmaf(svu.y, w1.x, o1ax); o1ay = fmaf(svu.z, w1.x, o1ay); o1az = fmaf(svu.w, w1.x, o1az);
        o1bx = fmaf(svu.y, w1.y, o1bx); o1by = fmaf(svu.z, w1.y, o1by); o1bz = fmaf(svu.w, w1.y, o1bz);
    }

    float* op = out + n * 256;
    int k0 = 2 * lane;
    op[k0]     += C_X * o0a;
    op[k0 + 1] += C_X * o0b;
    int b0 = 64 + 3 * k0;
    op[b0 + 0] += C_X * o1ax; op[b0 + 1] += C_X * o1ay; op[b0 + 2] += C_X * o1az;
    op[b0 + 3] += C_X * o1bx; op[b0 + 4] += C_X * o1by; op[b0 + 5] += C_X * o1bz;
}

// ============================================================================
extern "C" void kernel_launch(void* const* d_in, const int* in_sizes, int n_in,
                              void* d_out, int out_size)
{
    const float* node_input = (const float*)d_in[0];
    const float* node_attr  = (const float*)d_in[1];
    const float* node_deg   = (const float*)d_in[2];
    const float* edge_attr  = (const float*)d_in[3];
    const float* elen       = (const float*)d_in[4];
    const float* W_li0      = (const float*)d_in[5];
    const float* W_li1      = (const float*)d_in[6];
    const float* W_lm0      = (const float*)d_in[7];
    const float* W_lm1      = (const float*)d_in[8];
    const float* W_mlp1     = (const float*)d_in[9];
    const float* W_mlp2     = (const float*)d_in[10];
    const float* W_lo0      = (const float*)d_in[11];
    const float* W_lo1      = (const float*)d_in[12];
    const int*   edge_src   = (const int*)d_in[13];
    const int*   edge_dst   = (const int*)d_in[14];
    float* out = (float*)d_out;

    static int attr_set = 0;
    if (!attr_set) {
        cudaFuncSetAttribute(k_node, cudaFuncAttributeMaxDynamicSharedMemorySize, 73760);
        cudaFuncSetAttribute(k_pull, cudaFuncAttributeMaxDynamicSharedMemorySize, 81920);
        attr_set = 1;
    }

    k_node<<<N_NODES / 8, 256, 73760>>>(node_input, node_attr, node_deg,
                                        W_li0, W_li1, W_lm0, W_lm1, out);
    k_zero<<<(N_NODES + 255) / 256, 256>>>();
    k_hist<<<N_EDGES / 256, 256>>>(edge_dst);
    k_scan<<<1, 1024>>>();
    k_fill<<<N_EDGES / 256, 256>>>(edge_dst);
    k_mlp<<<N_EDGES / 64, 256>>>(elen, W_mlp1, W_mlp2);
    k_pull<<<N_NODES / 8, 256, 81920>>>(node_attr, node_deg, edge_attr, edge_src,
                                        W_lo0, W_lo1, out);
}

// round 3
// speedup vs baseline: 1.2634x; 1.2634x over previous
#include <cuda_runtime.h>
#include <cuda_bf16.h>
#include <cstdint>

#define N_NODES 20000
#define N_EDGES 320000

// ---------------- device scratch ------------------------------------------
__device__ float g_f [N_NODES * 256];       // f0|f1 (deg/attr/inv8 folded in)
__device__ float g_ew[N_EDGES * 256];       // per-edge MLP weights
__device__ int   g_cnt[N_NODES];
__device__ int   g_off[N_NODES + 1];
__device__ int   g_cur[N_NODES];
__device__ int   g_eid[N_EDGES];
__device__ __nv_bfloat16 g_W2t_h[256 * 112];  // W2^T hi, [n][k]
__device__ __nv_bfloat16 g_W2t_l[256 * 112];  // W2^T lo

// ---------------- constants -----------------------------------------------
#define INV8        0.125f
#define INV_SQRT10  0.3162277660168379f
#define INV10       0.1f
#define INV_SQRT3   0.5773502691896258f
#define INV_SQRT128 0.08838834764831845f
#define C_S         0.3826834323650898f
#define C_X         0.9238795325112867f

// ============================================================================
// K1: node self-interaction (unchanged)
// ============================================================================
__global__ __launch_bounds__(256) void k_node(
    const float* __restrict__ x, const float* __restrict__ attr,
    const float* __restrict__ deg,
    const float* __restrict__ Wli0, const float* __restrict__ Wli1,
    const float* __restrict__ Wlm0, const float* __restrict__ Wlm1,
    float* __restrict__ out)
{
    extern __shared__ float sm[];
    float* sWf0 = sm;
    float* sWf1 = sm + 4096;
    float* sWm0 = sm + 8192;
    float* sWm1 = sm + 12288;
    float* sx   = sm + 16384;     // 8 * 257

    int t = threadIdx.x;
    for (int i = t; i < 4096; i += 256) {
        sWf0[i] = Wli0[i]; sWf1[i] = Wli1[i];
        sWm0[i] = Wlm0[i]; sWm1[i] = Wlm1[i];
    }
    int nb = blockIdx.x * 8;
    for (int i = t; i < 8 * 256; i += 256) {
        int node = i >> 8, cc = i & 255;
        sx[node * 257 + cc] = x[(nb + node) * 256 + cc];
    }
    __syncthreads();

    int c = t;
    bool isS = (c < 64);
    int k = isS ? c : (c - 64) / 3;
    int m = isS ? 0 : (c - 64) % 3;
    int xoff = isS ? 0 : (64 + m);
    int xstr = isS ? 1 : 3;
    const float* wf = (isS ? sWf0 : sWf1) + k;
    const float* wm = (isS ? sWm0 : sWm1) + k;
    const float* xp = sx + xoff;

    float accf[8], accm[8];
#pragma unroll
    for (int i = 0; i < 8; i++) { accf[i] = 0.f; accm[i] = 0.f; }

#pragma unroll 4
    for (int u = 0; u < 64; u++) {
        float vf = wf[u * 64];
        float vm = wm[u * 64];
#pragma unroll
        for (int i = 0; i < 8; i++) {
            float xv = xp[i * 257 + u * xstr];
            accf[i] = fmaf(xv, vf, accf[i]);
            accm[i] = fmaf(xv, vm, accm[i]);
        }
    }
#pragma unroll
    for (int i = 0; i < 8; i++) {
        int n = nb + i;
        float a  = attr[n];
        float sf = INV8 * a * rsqrtf(deg[n]);
        float sc = INV8 * a * C_S;
        g_f[n * 256 + c] = accf[i] * sf;
        out[n * 256 + c] = accm[i] * sc;
    }
}

// ============================================================================
// CSR build kernels (unchanged)
// ============================================================================
__global__ __launch_bounds__(256) void k_zero() {
    int i = blockIdx.x * 256 + threadIdx.x;
    if (i < N_NODES) g_cnt[i] = 0;
}
__global__ __launch_bounds__(256) void k_hist(const int* __restrict__ dst) {
    int i = blockIdx.x * 256 + threadIdx.x;
    if (i < N_EDGES) atomicAdd(&g_cnt[dst[i]], 1);
}
__global__ __launch_bounds__(1024) void k_scan() {
    int t = threadIdx.x, lane = t & 31, wid = t >> 5;
    __shared__ int wsum[32];
    __shared__ int carry;
    if (t == 0) carry = 0;
    __syncthreads();
    for (int base = 0; base < N_NODES; base += 1024) {
        int i = base + t;
        int v = (i < N_NODES) ? g_cnt[i] : 0;
        int x = v;
#pragma unroll
        for (int d = 1; d < 32; d <<= 1) {
            int y = __shfl_up_sync(0xffffffffu, x, d);
            if (lane >= d) x += y;
        }
        if (lane == 31) wsum[wid] = x;
        __syncthreads();
        if (wid == 0) {
            int s = wsum[lane];
#pragma unroll
            for (int d = 1; d < 32; d <<= 1) {
                int y = __shfl_up_sync(0xffffffffu, s, d);
                if (lane >= d) s += y;
            }
            wsum[lane] = s;
        }
        __syncthreads();
        int excl = carry + (wid ? wsum[wid - 1] : 0) + x - v;
        if (i < N_NODES) { g_off[i] = excl; g_cur[i] = excl; }
        int tot = wsum[31];
        __syncthreads();
        if (t == 0) carry += tot;
        __syncthreads();
    }
    if (t == 0) g_off[N_NODES] = carry;
}
__global__ __launch_bounds__(256) void k_fill(const int* __restrict__ dst) {
    int i = blockIdx.x * 256 + threadIdx.x;
    if (i < N_EDGES) {
        int d = dst[i];
        int p = atomicAdd(&g_cur[d], 1);
        g_eid[p] = i;
    }
}

// ============================================================================
// K-prep: split W2^T into bf16 hi/lo, [n=256][k=112] (k >= 100 zero)
// ============================================================================
__global__ __launch_bounds__(256) void k_prep(const float* __restrict__ W2) {
    int idx = blockIdx.x * 256 + threadIdx.x;   // 112 blocks -> 28672
    if (idx >= 256 * 112) return;
    int n = idx / 112, k = idx - n * 112;
    float v = (k < 100) ? W2[k * 256 + n] : 0.0f;
    __nv_bfloat16 h = __float2bfloat16(v);
    __nv_bfloat16 l = __float2bfloat16(v - __bfloat162float(h));
    g_W2t_h[idx] = h;
    g_W2t_l[idx] = l;
}

// ============================================================================
// K2 (HMMA): ew = silu(elen @ W1 / sqrt(10)) @ W2 / 10   -> g_ew
// Block = 128 edges x 256 outs, K padded 100->112.
// bf16 3-split via mma.sync.m16n8k16 (compiles for plain sm_103).
// SMEM layout: rows padded to 120 bf16 (240B) -> conflict-free frag LDS.
// ============================================================================
#define RSTR 120                       // padded row stride (bf16 elems)
#define OFF_W1 0                       // 1000 floats  = 4000 B
#define OFF_AH 4096                    // 128*240      = 30720
#define OFF_AL 34816
#define OFF_BH 65536                   // 256*240      = 61440
#define OFF_BL 126976
#define MLP_SMEM 188416

__device__ __forceinline__ void mma16816(
    float& c0, float& c1, float& c2, float& c3,
    uint32_t a0, uint32_t a1, uint32_t a2, uint32_t a3,
    uint32_t b0, uint32_t b1)
{
    asm volatile(
        "mma.sync.aligned.m16n8k16.row.col.f32.bf16.bf16.f32 "
        "{%0,%1,%2,%3}, {%4,%5,%6,%7}, {%8,%9}, {%0,%1,%2,%3};"
        : "+f"(c0), "+f"(c1), "+f"(c2), "+f"(c3)
        : "r"(a0), "r"(a1), "r"(a2), "r"(a3), "r"(b0), "r"(b1));
}

__device__ __forceinline__ uint32_t pack_bf2(__nv_bfloat16 a, __nv_bfloat16 b) {
    return (uint32_t)__bfloat16_as_ushort(a) |
           ((uint32_t)__bfloat16_as_ushort(b) << 16);
}

__global__ __launch_bounds__(256, 1) void k_mlp_mma(
    const float* __restrict__ elen, const float* __restrict__ W1)
{
    extern __shared__ char smc[];
    float* sW1 = (float*)(smc + OFF_W1);
    __nv_bfloat16* sAh = (__nv_bfloat16*)(smc + OFF_AH);
    __nv_bfloat16* sAl = (__nv_bfloat16*)(smc + OFF_AL);
    __nv_bfloat16* sBh = (__nv_bfloat16*)(smc + OFF_BH);
    __nv_bfloat16* sBl = (__nv_bfloat16*)(smc + OFF_BL);

    int t = threadIdx.x, wid = t >> 5, lane = t & 31;
    int e0 = blockIdx.x * 128;

    // ---- copy W1, copy W2t hi/lo into padded smem ----
    for (int i = t; i < 1000; i += 256) sW1[i] = W1[i];
    {
        int n = t;  // 0..255, one B row each (112 bf16 = 14 uint4)
        const uint4* srcH = (const uint4*)(g_W2t_h + n * 112);
        const uint4* srcL = (const uint4*)(g_W2t_l + n * 112);
        uint4* dstH = (uint4*)(sBh + n * RSTR);
        uint4* dstL = (uint4*)(sBl + n * RSTR);
#pragma unroll
        for (int j = 0; j < 14; j++) { dstH[j] = srcH[j]; dstL[j] = srcL[j]; }
    }

    // ---- layer 1 + silu -> A hi/lo (rows = edges, cols = k, padded) ----
    {
        int e  = t & 127;
        int kh = t >> 7;               // 0 or 1 -> k in [56*kh, 56*kh+56)
        float el[10];
        const float* ep = elen + (e0 + e) * 10;
#pragma unroll
        for (int b = 0; b < 10; b++) el[b] = __ldg(ep + b);
        int kbase = 56 * kh;
#pragma unroll 1
        for (int kk = 0; kk < 56; kk += 2) {
            float h2[2];
#pragma unroll
            for (int jj = 0; jj < 2; jj++) {
                int k = kbase + kk + jj;
                float hv = 0.f;
                if (k < 100) {
                    float acc = 0.f;
#pragma unroll
                    for (int b = 0; b < 10; b++)
                        acc = fmaf(el[b], sW1[b * 100 + k], acc);
                    float xx = acc * INV_SQRT10;
                    hv = xx / (1.0f + __expf(-xx));
                }
                h2[jj] = hv;
            }
            __nv_bfloat16 h0 = __float2bfloat16(h2[0]);
            __nv_bfloat16 h1 = __float2bfloat16(h2[1]);
            __nv_bfloat16 l0 = __float2bfloat16(h2[0] - __bfloat162float(h0));
            __nv_bfloat16 l1 = __float2bfloat16(h2[1] - __bfloat162float(h1));
            int off = e * RSTR + kbase + kk;
            *(uint32_t*)(sAh + off) = pack_bf2(h0, h1);
            *(uint32_t*)(sAl + off) = pack_bf2(l0, l1);
        }
    }
    __syncthreads();

    // ---- main loop: warp tile 32(M) x 128(N); 2 m-sub x 16 n-sub ----
    int wm = wid & 3;                  // rows [32*wm, +32)
    int wn = wid >> 2;                 // cols [128*wn, +128)
    int rowA = 32 * wm + (lane >> 2);  // a0 row (a1/a3: +8); +16 for mt=1
    int kA   = (lane & 3) * 2;
    int rowB = 128 * wn + (lane >> 2); // b0 n (per n-sub: +8*nt)

    float acc[2][16][4];
#pragma unroll
    for (int mt = 0; mt < 2; mt++)
#pragma unroll
        for (int nt = 0; nt < 16; nt++)
#pragma unroll
            for (int j = 0; j < 4; j++) acc[mt][nt][j] = 0.f;

    const __nv_bfloat16* Aptr[3] = { sAh, sAh, sAl };
    const __nv_bfloat16* Bptr[3] = { sBh, sBl, sBh };

#pragma unroll 1
    for (int ks = 0; ks < 7; ks++) {
        int k0 = ks * 16 + kA;
#pragma unroll
        for (int p = 0; p < 3; p++) {
            const __nv_bfloat16* A = Aptr[p] + rowA * RSTR + k0;
            const __nv_bfloat16* B = Bptr[p] + rowB * RSTR + k0;
            uint32_t a[2][4];
#pragma unroll
            for (int mt = 0; mt < 2; mt++) {
                const __nv_bfloat16* Am = A + mt * 16 * RSTR;
                a[mt][0] = *(const uint32_t*)(Am);
                a[mt][1] = *(const uint32_t*)(Am + 8 * RSTR);
                a[mt][2] = *(const uint32_t*)(Am + 8);
                a[mt][3] = *(const uint32_t*)(Am + 8 * RSTR + 8);
            }
#pragma unroll
            for (int nt = 0; nt < 16; nt++) {
                const __nv_bfloat16* Bn = B + nt * 8 * RSTR;
                uint32_t b0 = *(const uint32_t*)(Bn);
                uint32_t b1 = *(const uint32_t*)(Bn + 8);
#pragma unroll
                for (int mt = 0; mt < 2; mt++)
                    mma16816(acc[mt][nt][0], acc[mt][nt][1],
                             acc[mt][nt][2], acc[mt][nt][3],
                             a[mt][0], a[mt][1], a[mt][2], a[mt][3], b0, b1);
            }
        }
    }

    // ---- epilogue: scale + store ----
    int erow = e0 + 32 * wm + (lane >> 2);
    int col  = 128 * wn + (lane & 3) * 2;
#pragma unroll
    for (int mt = 0; mt < 2; mt++) {
#pragma unroll
        for (int nt = 0; nt < 16; nt++) {
            int c = col + nt * 8;
            float* p0 = g_ew + (size_t)(erow + mt * 16) * 256 + c;
            float* p1 = p0 + 8 * 256;
            *(float2*)p0 = make_float2(acc[mt][nt][0] * INV10, acc[mt][nt][1] * INV10);
            *(float2*)p1 = make_float2(acc[mt][nt][2] * INV10, acc[mt][nt][3] * INV10);
        }
    }
}

// ============================================================================
// K3: pull kernel (unchanged)
// ============================================================================
__global__ __launch_bounds__(256) void k_pull(
    const float* __restrict__ attr, const float* __restrict__ deg,
    const float* __restrict__ eattr, const int* __restrict__ esrc,
    const float* __restrict__ Wlo0, const float* __restrict__ Wlo1,
    float* __restrict__ out)
{
    extern __shared__ float sm[];
    float* sW0  = sm;
    float* sW1  = sm + 8192;
    float* s_sv = sm + 16384;

    int t = threadIdx.x;
    for (int i = t; i < 8192; i += 256) { sW0[i] = Wlo0[i]; sW1[i] = Wlo1[i]; }
    __syncthreads();

    int w = t >> 5, lane = t & 31;
    int n = blockIdx.x * 8 + w;
    int beg = g_off[n], end = g_off[n + 1];

    float sa0 = 0.f, sa1 = 0.f, sb0 = 0.f, sb1 = 0.f;
    float va0x=0.f,va0y=0.f,va0z=0.f, va1x=0.f,va1y=0.f,va1z=0.f;
    float vb0x=0.f,vb0y=0.f,vb0z=0.f, vb1x=0.f,vb1y=0.f,vb1z=0.f;

    for (int ei = beg; ei < end; ei++) {
        int e   = g_eid[ei];
        int src = esrc[e];
        float4 ea = __ldg((const float4*)(eattr) + e);
        float y0 = ea.x, y1x = ea.y, y1y = ea.z, y1z = ea.w;
        const float* fp = g_f  + src * 256;
        const float* wp = g_ew + (size_t)e * 256;

        float2 G0 = *(const float2*)(fp + 2 * lane);
        float2 Ga = *(const float2*)(fp + 64 + 6 * lane);
        float2 Gb = *(const float2*)(fp + 64 + 6 * lane + 2);
        float2 Gc = *(const float2*)(fp + 64 + 6 * lane + 4);
        float2 WA = *(const float2*)(wp + 2 * lane);
        float2 WB = *(const float2*)(wp + 64 + 2 * lane);
        float2 WC = *(const float2*)(wp + 128 + 2 * lane);
        float2 WD = *(const float2*)(wp + 192 + 2 * lane);

        {
            float g1x = Ga.x, g1y = Ga.y, g1z = Gb.x;
            float d3 = fmaf(g1x, y1x, fmaf(g1y, y1y, g1z * y1z));
            sa0 = fmaf(WA.x * G0.x, y0, sa0);
            sb0 = fmaf(WB.x, d3, sb0);
            float cg = WC.x * G0.x;
            va0x = fmaf(cg, y1x, va0x); va0y = fmaf(cg, y1y, va0y); va0z = fmaf(cg, y1z, va0z);
            float dg = WD.x * y0;
            vb0x = fmaf(dg, g1x, vb0x); vb0y = fmaf(dg, g1y, vb0y); vb0z = fmaf(dg, g1z, vb0z);
        }
        {
            float g1x = Gb.y, g1y = Gc.x, g1z = Gc.y;
            float d3 = fmaf(g1x, y1x, fmaf(g1y, y1y, g1z * y1z));
            sa1 = fmaf(WA.y * G0.y, y0, sa1);
            sb1 = fmaf(WB.y, d3, sb1);
            float cg = WC.y * G0.y;
            va1x = fmaf(cg, y1x, va1x); va1y = fmaf(cg, y1y, va1y); va1z = fmaf(cg, y1z, va1z);
            float dg = WD.y * y0;
            vb1x = fmaf(dg, g1x, vb1x); vb1y = fmaf(dg, g1y, vb1y); vb1z = fmaf(dg, g1z, vb1z);
        }
    }

    float a = attr[n];
    float scale = a * rsqrtf(deg[n]) * INV_SQRT128;
    float scb   = scale * INV_SQRT3;
    float4* sv = (float4*)(s_sv + w * 512);
    sv[2 * lane]      = make_float4(sa0 * scale, va0x * scale, va0y * scale, va0z * scale);
    sv[2 * lane + 1]  = make_float4(sa1 * scale, va1x * scale, va1y * scale, va1z * scale);
    sv[64 + 2 * lane]     = make_float4(sb0 * scb, vb0x * scale, vb0y * scale, vb0z * scale);
    sv[64 + 2 * lane + 1] = make_float4(sb1 * scb, vb1x * scale, vb1y * scale, vb1z * scale);
    __syncwarp();

    float o0a = 0.f, o0b = 0.f;
    float o1ax=0.f,o1ay=0.f,o1az=0.f, o1bx=0.f,o1by=0.f,o1bz=0.f;
#pragma unroll 4
    for (int u = 0; u < 128; u++) {
        float4 svu = sv[u];
        float2 w0 = *(const float2*)(sW0 + u * 64 + 2 * lane);
        float2 w1 = *(const float2*)(sW1 + u * 64 + 2 * lane);
        o0a = fmaf(svu.x, w0.x, o0a);
        o0b = fmaf(svu.x, w0.y, o0b);
        o1ax = fmaf(svu.y, w1.x, o1ax); o1ay = fmaf(svu.z, w1.x, o1ay); o1az = fmaf(svu.w, w1.x, o1az);
        o1bx = fmaf(svu.y, w1.y, o1bx); o1by = fmaf(svu.z, w1.y, o1by); o1bz = fmaf(svu.w, w1.y, o1bz);
    }

    float* op = out + n * 256;
    int k0 = 2 * lane;
    op[k0]     += C_X * o0a;
    op[k0 + 1] += C_X * o0b;
    int b0 = 64 + 3 * k0;
    op[b0 + 0] += C_X * o1ax; op[b0 + 1] += C_X * o1ay; op[b0 + 2] += C_X * o1az;
    op[b0 + 3] += C_X * o1bx; op[b0 + 4] += C_X * o1by; op[b0 + 5] += C_X * o1bz;
}

// ============================================================================
extern "C" void kernel_launch(void* const* d_in, const int* in_sizes, int n_in,
                              void* d_out, int out_size)
{
    const float* node_input = (const float*)d_in[0];
    const float* node_attr  = (const float*)d_in[1];
    const float* node_deg   = (const float*)d_in[2];
    const float* edge_attr  = (const float*)d_in[3];
    const float* elen       = (const float*)d_in[4];
    const float* W_li0      = (const float*)d_in[5];
    const float* W_li1      = (const float*)d_in[6];
    const float* W_lm0      = (const float*)d_in[7];
    const float* W_lm1      = (const float*)d_in[8];
    const float* W_mlp1     = (const float*)d_in[9];
    const float* W_mlp2     = (const float*)d_in[10];
    const float* W_lo0      = (const float*)d_in[11];
    const float* W_lo1      = (const float*)d_in[12];
    const int*   edge_src   = (const int*)d_in[13];
    const int*   edge_dst   = (const int*)d_in[14];
    float* out = (float*)d_out;

    static int attr_set = 0;
    if (!attr_set) {
        cudaFuncSetAttribute(k_node, cudaFuncAttributeMaxDynamicSharedMemorySize, 73760);
        cudaFuncSetAttribute(k_pull, cudaFuncAttributeMaxDynamicSharedMemorySize, 81920);
        cudaFuncSetAttribute(k_mlp_mma, cudaFuncAttributeMaxDynamicSharedMemorySize, MLP_SMEM);
        attr_set = 1;
    }

    k_node<<<N_NODES / 8, 256, 73760>>>(node_input, node_attr, node_deg,
                                        W_li0, W_li1, W_lm0, W_lm1, out);
    k_zero<<<(N_NODES + 255) / 256, 256>>>();
    k_hist<<<N_EDGES / 256, 256>>>(edge_dst);
    k_scan<<<1, 1024>>>();
    k_fill<<<N_EDGES / 256, 256>>>(edge_dst);
    k_prep<<<112, 256>>>(W_mlp2);
    k_mlp_mma<<<N_EDGES / 128, 256, MLP_SMEM>>>(elen, W_mlp1);
    k_pull<<<N_NODES / 8, 256, 81920>>>(node_attr, node_deg, edge_attr, edge_src,
                                        W_lo0, W_lo1, out);
}